// round 15
// baseline (speedup 1.0000x reference)
#include <cuda_runtime.h>
#include <cuda_bf16.h>
#include <cstdint>

#define Bb 32
#define Cc 64
#define Lc 8192
#define Mm (Bb * Lc)
#define NBLK 296                 // 148 SMs x 2 resident blocks
#define NT_G 2048                // gram tiles (128 cols each)
#define NT_A 2048                // apply tiles (128 cols each)
#define ROWB 136                 // bf16 tile row stride (elements) -> 272 B
#define WROW 264                 // wmDual smem row stride (bf16 elements)
#define EPSV 1e-5f

__device__ __align__(16) float g_gram_part[NBLK * 4096];
__device__ __align__(16) float g_sum_part[NBLK * 64];
__device__ __align__(16) float g_gram[4096];
__device__ __align__(16) float g_mean[64];
__device__ __align__(16) __nv_bfloat16 g_wmDual[64 * 256];   // [c][ wh | wl | wl | wh ]
__device__ __align__(16) float g_bias[64];

// ---------------- f32x2 / smem helpers ----------------
__device__ __forceinline__ unsigned long long dup2(float v) {
    unsigned long long r; asm("mov.b64 %0, {%1, %1};" : "=l"(r) : "f"(v)); return r;
}
__device__ __forceinline__ void fma2(unsigned long long& d, unsigned long long a,
                                     unsigned long long b) {
    asm("fma.rn.f32x2 %0, %1, %2, %0;" : "+l"(d) : "l"(a), "l"(b));
}
__device__ __forceinline__ float2 unpk(unsigned long long v) {
    float2 r; asm("mov.b64 {%0, %1}, %2;" : "=f"(r.x), "=f"(r.y) : "l"(v)); return r;
}
__device__ __forceinline__ uint32_t smem_u32(const void* p) {
    uint32_t a;
    asm("{ .reg .u64 t; cvta.to.shared.u64 t, %1; cvt.u32.u64 %0, t; }" : "=r"(a) : "l"(p));
    return a;
}

// ---------------- mma.sync helpers (baseline PTX, sm_80+) ----------------
__device__ __forceinline__ void ldsm_x4(uint32_t addr, uint32_t& r0, uint32_t& r1,
                                        uint32_t& r2, uint32_t& r3) {
    asm volatile("ldmatrix.sync.aligned.m8n8.x4.shared.b16 {%0,%1,%2,%3}, [%4];"
                 : "=r"(r0), "=r"(r1), "=r"(r2), "=r"(r3) : "r"(addr));
}
__device__ __forceinline__ void ldsm_x4t(uint32_t addr, uint32_t& r0, uint32_t& r1,
                                         uint32_t& r2, uint32_t& r3) {
    asm volatile("ldmatrix.sync.aligned.m8n8.x4.trans.shared.b16 {%0,%1,%2,%3}, [%4];"
                 : "=r"(r0), "=r"(r1), "=r"(r2), "=r"(r3) : "r"(addr));
}
__device__ __forceinline__ void mma16816(float* d, uint32_t a0, uint32_t a1,
                                         uint32_t a2, uint32_t a3,
                                         uint32_t b0, uint32_t b1) {
    asm volatile(
        "mma.sync.aligned.m16n8k16.row.col.f32.bf16.bf16.f32 "
        "{%0,%1,%2,%3}, {%4,%5,%6,%7}, {%8,%9}, {%0,%1,%2,%3};"
        : "+f"(d[0]), "+f"(d[1]), "+f"(d[2]), "+f"(d[3])
        : "r"(a0), "r"(a1), "r"(a2), "r"(a3), "r"(b0), "r"(b1));
}
__device__ __forceinline__ uint32_t bfpack(float lo, float hi) {
    uint32_t r; asm("cvt.rn.bf16x2.f32 %0, %2, %1;" : "=r"(r) : "f"(lo), "f"(hi));
    return r;
}
__device__ __forceinline__ void sts64(uint32_t a, uint32_t v0, uint32_t v1) {
    asm volatile("st.shared.v2.b32 [%0], {%1, %2};" :: "r"(a), "r"(v0), "r"(v1));
}
// convert one float4 to (hi pair, lo pair) bf16x2 and store to stacked tile
__device__ __forceinline__ void split_store(uint32_t hi_a, uint32_t lo_a, float4 v) {
    uint32_t h0 = bfpack(v.x, v.y);
    uint32_t h1 = bfpack(v.z, v.w);
    float r0 = v.x - __uint_as_float(h0 << 16);
    float r1 = v.y - __uint_as_float(h0 & 0xffff0000u);
    float r2 = v.z - __uint_as_float(h1 << 16);
    float r3 = v.w - __uint_as_float(h1 & 0xffff0000u);
    sts64(hi_a, h0, h1);
    sts64(lo_a, bfpack(r0, r1), bfpack(r2, r3));
}

// ================= Kernel 1: Gram via mma.sync, register-prefetch pipeline ==========
// Per tile: convert prefetched regs -> stacked bf16 tile (hi rows 0-63, lo 64-127);
// sync; issue LDG prefetch of tile i+1 into regs (hides under mma); mma; sync.
// smem: bf16 tile [128][ROWB] @0 (34816 B); epilogue D [128][132] fp32 (67584 B)
// overlays it. SMEM_G = 67584 -> occ 2 (reg-bound anyway).
#define SMEM_G 67584

__global__ __launch_bounds__(256) void gram_kernel(const float* __restrict__ X) {
    extern __shared__ float gsm[];
    const int tid = threadIdx.x;
    const int lane = tid & 31, w = tid >> 5;
    const int bid = blockIdx.x;
    const int ts = (bid * NT_G) / NBLK;
    const int te = ((bid + 1) * NT_G) / NBLK;

    const uint32_t bfbase = smem_u32(gsm);

    const int cc = tid >> 2;
    const int lseg = (tid & 3) * 32;
    const uint32_t hi_addr = bfbase + (uint32_t)(cc * ROWB + lseg) * 2;
    const uint32_t lo_addr = hi_addr + (uint32_t)(64 * ROWB) * 2;
    const float* Xrow = X + (size_t)cc * Lc + lseg;      // + bb*Cc*Lc + l0

    const int m0 = w * 16;
    const int arow = m0 + (lane & 7) + ((lane >> 3) & 1) * 8;
    const int acol = (lane >> 4) * 8;
    const uint32_t a_addr = bfbase + (uint32_t)(arow * ROWB + acol) * 2;
    const int brow = (lane & 7) + (lane >> 4) * 8;
    const int bcol = ((lane >> 3) & 1) * 8;
    const uint32_t b_addr = bfbase + (uint32_t)(brow * ROWB + bcol) * 2;

    float acc[16][4];
    #pragma unroll
    for (int t = 0; t < 16; t++) { acc[t][0] = acc[t][1] = acc[t][2] = acc[t][3] = 0.f; }
    float csum = 0.f;

    float4 xv[8];
    {   // prefetch tile ts
        const float* p = Xrow + (size_t)(ts >> 6) * (Cc * Lc) + ((ts & 63) << 7);
        #pragma unroll
        for (int j = 0; j < 8; j++) xv[j] = *(const float4*)&p[j * 4];
    }

    #pragma unroll 1
    for (int i = ts; i < te; i++) {
        // ---- convert regs -> stacked bf16 tile (+ channel sums) ----
        #pragma unroll
        for (int j = 0; j < 8; j++) {
            float4 v = xv[j];
            csum += (v.x + v.y) + (v.z + v.w);
            split_store(hi_addr + j * 8, lo_addr + j * 8, v);
        }
        __syncthreads();

        // ---- prefetch tile i+1 (LDG latency hides under mma below) ----
        if (i + 1 < te) {
            const float* p = Xrow + (size_t)((i + 1) >> 6) * (Cc * Lc)
                             + (((i + 1) & 63) << 7);
            #pragma unroll
            for (int j = 0; j < 8; j++) xv[j] = *(const float4*)&p[j * 4];
        }

        // ---- HMMA: warp w computes D rows m0..m0+15, all 128 cols ----
        #pragma unroll
        for (int ks = 0; ks < 8; ks++) {
            const uint32_t koff = (uint32_t)(ks * 32);
            uint32_t a0, a1, a2, a3;
            ldsm_x4(a_addr + koff, a0, a1, a2, a3);
            #pragma unroll
            for (int nb = 0; nb < 8; nb++) {
                uint32_t b0, b1, b2, b3;
                ldsm_x4(b_addr + (uint32_t)(nb * 16 * ROWB * 2) + koff, b0, b1, b2, b3);
                mma16816(acc[2 * nb], a0, a1, a2, a3, b0, b1);
                mma16816(acc[2 * nb + 1], a0, a1, a2, a3, b2, b3);
            }
        }
        __syncthreads();    // tile fully consumed before next convert overwrites
    }

    // ---- epilogue: D -> smem, fold quadrants ----
    float* Dsm = gsm;
    {
        const int row_in = lane >> 2, kq = lane & 3;
        #pragma unroll
        for (int nt = 0; nt < 16; nt++) {
            float* dr = Dsm + (m0 + row_in) * 132 + nt * 8 + 2 * kq;
            dr[0] = acc[nt][0];
            dr[1] = acc[nt][1];
            dr[132 * 8] = acc[nt][2];
            dr[132 * 8 + 1] = acc[nt][3];
        }
    }
    __syncthreads();
    {
        float* gp = g_gram_part + (size_t)bid * 4096;
        for (int e = tid; e < 4096; e += 256) {
            int c1 = e >> 6, c2 = e & 63;
            gp[e] = (Dsm[c1 * 132 + c2] + Dsm[c1 * 132 + c2 + 64])
                  + (Dsm[(c1 + 64) * 132 + c2] + Dsm[(c1 + 64) * 132 + c2 + 64]);
        }
    }
    csum += __shfl_down_sync(0xffffffffu, csum, 2, 4);
    csum += __shfl_down_sync(0xffffffffu, csum, 1, 4);
    if ((tid & 3) == 0) g_sum_part[bid * 64 + (tid >> 2)] = csum;
}

// ================= Kernel 2: reduction (unchanged) =================
__global__ __launch_bounds__(256) void reduce_kernel() {
    __shared__ float s[256];
    const int tid = threadIdx.x;
    if (blockIdx.x < 128) {
        const int e = blockIdx.x * 32 + (tid & 31);
        const int ch = tid >> 5;
        const float* base = g_gram_part + (size_t)(ch * 37) * 4096 + e;
        float a0 = 0, a1 = 0, a2 = 0, a3 = 0;
        #pragma unroll 1
        for (int q = 0; q < 36; q += 4) {
            a0 += base[(size_t)(q + 0) * 4096];
            a1 += base[(size_t)(q + 1) * 4096];
            a2 += base[(size_t)(q + 2) * 4096];
            a3 += base[(size_t)(q + 3) * 4096];
        }
        a0 += base[(size_t)36 * 4096];
        s[tid] = (a0 + a1) + (a2 + a3);
        __syncthreads();
        if (tid < 32) {
            float r = 0.f;
            #pragma unroll
            for (int c2 = 0; c2 < 8; c2++) r += s[c2 * 32 + tid];
            g_gram[blockIdx.x * 32 + tid] = r;
        }
    } else {
        const int c = tid & 63, ch = tid >> 6;
        const float* base = g_sum_part + (size_t)(ch * 74) * 64 + c;
        float a0 = 0, a1 = 0;
        #pragma unroll 1
        for (int q = 0; q < 74; q += 2) {
            a0 += base[(q + 0) * 64];
            a1 += base[(q + 1) * 64];
        }
        s[tid] = a0 + a1;
        __syncthreads();
        if (tid < 64) {
            float r = (s[tid] + s[64 + tid]) + (s[128 + tid] + s[192 + tid]);
            g_mean[tid] = r * (1.0f / (float)Mm);
        }
    }
}

// ================= Kernel 3: Sigma + Newton-Schulz (+ wmDual emit) =================
#define SOLVER_SMEM (4 * 4096 * (int)sizeof(float))

__global__ __launch_bounds__(256) void solver_kernel() {
    extern __shared__ float ssm[];
    float* P = ssm;
    float* S = ssm + 4096;
    float* U = ssm + 8192;
    float* V = ssm + 12288;
    const int tid = threadIdx.x;
    const float inv_m = 1.0f / (float)Mm;

    for (int e = tid; e < 4096; e += 256) {
        int c1 = e >> 6, c2 = e & 63;
        S[e] = g_gram[e] * inv_m - g_mean[c1] * g_mean[c2] + ((c1 == c2) ? EPSV : 0.0f);
    }
    __syncthreads();
    float tr = 0.f;
    #pragma unroll
    for (int c = 0; c < 64; c++) tr += S[c * 65];
    const float rTr = 1.0f / tr;
    __syncthreads();
    for (int e = tid; e < 4096; e += 256) {
        S[e] *= rTr;
        int c1 = e >> 6, c2 = e & 63;
        P[e] = (c1 == c2) ? 1.0f : 0.0f;
    }
    __syncthreads();

    const int ty = tid >> 4, tx = tid & 15;
    const int r = ty * 4, cb = tx * 4;

    #pragma unroll 1
    for (int it = 0; it < 5; it++) {
        unsigned long long aU[4][2] = {}, aV[4][2] = {};
        #pragma unroll
        for (int k4 = 0; k4 < 16; k4++) {
            float4 a0 = *(const float4*)&P[(r + 0) * 64 + k4 * 4];
            float4 a1 = *(const float4*)&P[(r + 1) * 64 + k4 * 4];
            float4 a2 = *(const float4*)&P[(r + 2) * 64 + k4 * 4];
            float4 a3 = *(const float4*)&P[(r + 3) * 64 + k4 * 4];
            #pragma unroll
            for (int kk = 0; kk < 4; kk++) {
                float f0 = kk == 0 ? a0.x : kk == 1 ? a0.y : kk == 2 ? a0.z : a0.w;
                float f1 = kk == 0 ? a1.x : kk == 1 ? a1.y : kk == 2 ? a1.z : a1.w;
                float f2 = kk == 0 ? a2.x : kk == 1 ? a2.y : kk == 2 ? a2.z : a2.w;
                float f3 = kk == 0 ? a3.x : kk == 1 ? a3.y : kk == 2 ? a3.z : a3.w;
                const int k = k4 * 4 + kk;
                ulonglong2 bp = *(const ulonglong2*)&P[k * 64 + cb];
                ulonglong2 bs = *(const ulonglong2*)&S[k * 64 + cb];
                unsigned long long d;
                d = dup2(f0);
                fma2(aU[0][0], d, bp.x); fma2(aU[0][1], d, bp.y);
                fma2(aV[0][0], d, bs.x); fma2(aV[0][1], d, bs.y);
                d = dup2(f1);
                fma2(aU[1][0], d, bp.x); fma2(aU[1][1], d, bp.y);
                fma2(aV[1][0], d, bs.x); fma2(aV[1][1], d, bs.y);
                d = dup2(f2);
                fma2(aU[2][0], d, bp.x); fma2(aU[2][1], d, bp.y);
                fma2(aV[2][0], d, bs.x); fma2(aV[2][1], d, bs.y);
                d = dup2(f3);
                fma2(aU[3][0], d, bp.x); fma2(aU[3][1], d, bp.y);
                fma2(aV[3][0], d, bs.x); fma2(aV[3][1], d, bs.y);
            }
        }
        #pragma unroll
        for (int i = 0; i < 4; i++) {
            float2 u0 = unpk(aU[i][0]), u1 = unpk(aU[i][1]);
            float2 v0 = unpk(aV[i][0]), v1 = unpk(aV[i][1]);
            *(float4*)&U[(r + i) * 64 + cb] = make_float4(u0.x, u0.y, u1.x, u1.y);
            *(float4*)&V[(r + i) * 64 + cb] = make_float4(v0.x, v0.y, v1.x, v1.y);
        }
        __syncthreads();

        unsigned long long aW[4][2] = {};
        #pragma unroll
        for (int k4 = 0; k4 < 16; k4++) {
            float4 a0 = *(const float4*)&U[(r + 0) * 64 + k4 * 4];
            float4 a1 = *(const float4*)&U[(r + 1) * 64 + k4 * 4];
            float4 a2 = *(const float4*)&U[(r + 2) * 64 + k4 * 4];
            float4 a3 = *(const float4*)&U[(r + 3) * 64 + k4 * 4];
            #pragma unroll
            for (int kk = 0; kk < 4; kk++) {
                float f0 = kk == 0 ? a0.x : kk == 1 ? a0.y : kk == 2 ? a0.z : a0.w;
                float f1 = kk == 0 ? a1.x : kk == 1 ? a1.y : kk == 2 ? a1.z : a1.w;
                float f2 = kk == 0 ? a2.x : kk == 1 ? a2.y : kk == 2 ? a2.z : a2.w;
                float f3 = kk == 0 ? a3.x : kk == 1 ? a3.y : kk == 2 ? a3.z : a3.w;
                ulonglong2 bv = *(const ulonglong2*)&V[(k4 * 4 + kk) * 64 + cb];
                unsigned long long d;
                d = dup2(f0); fma2(aW[0][0], d, bv.x); fma2(aW[0][1], d, bv.y);
                d = dup2(f1); fma2(aW[1][0], d, bv.x); fma2(aW[1][1], d, bv.y);
                d = dup2(f2); fma2(aW[2][0], d, bv.x); fma2(aW[2][1], d, bv.y);
                d = dup2(f3); fma2(aW[3][0], d, bv.x); fma2(aW[3][1], d, bv.y);
            }
        }
        #pragma unroll
        for (int i = 0; i < 4; i++) {
            float2 w0 = unpk(aW[i][0]), w1 = unpk(aW[i][1]);
            float* pr = &P[(r + i) * 64 + cb];
            float4 pv = *(float4*)pr;
            *(float4*)pr = make_float4(1.5f * pv.x - 0.5f * w0.x,
                                       1.5f * pv.y - 0.5f * w0.y,
                                       1.5f * pv.z - 0.5f * w1.x,
                                       1.5f * pv.w - 0.5f * w1.y);
        }
        __syncthreads();
    }

    const float sq = sqrtf(rTr);
    for (int e = tid; e < 4096; e += 256) {
        int c = e >> 6, k = e & 63;
        float wv = P[c * 64 + k] * sq;
        __nv_bfloat16 h = __float2bfloat16(wv);
        __nv_bfloat16 l = __float2bfloat16(wv - __bfloat162float(h));
        g_wmDual[c * 256 + k] = h;
        g_wmDual[c * 256 + 64 + k] = l;
        g_wmDual[c * 256 + 128 + k] = l;
        g_wmDual[c * 256 + 192 + k] = h;
    }
    if (tid < 64) {
        float bs = 0.f;
        #pragma unroll 8
        for (int cp = 0; cp < 64; cp++) bs += P[tid * 64 + cp] * g_mean[cp];
        g_bias[tid] = bs * sq;
    }
}

// ================= Kernel 4: apply via mma.sync dual-stack, reg-prefetch ==========
// smem: wmDual [64][WROW] bf16 @0 (33792 B); B tile [128][ROWB] @33792 (34816 B);
// bias @68608. Total 68864. Pipeline identical to gram: convert regs -> B; sync;
// prefetch next tile to regs; mma; epilogue (regs only); sync.
#define BT_OFF 33792
#define BIAS_OFF 68608
#define SMEM_A2 68864

__global__ __launch_bounds__(256) void apply_kernel(const float* __restrict__ X,
                                                    float* __restrict__ Y) {
    extern __shared__ float sm[];
    const int tid = threadIdx.x;
    const int lane = tid & 31, w = tid >> 5;
    const int bid = blockIdx.x;
    const int ts = (bid * NT_A) / NBLK;
    const int te = ((bid + 1) * NT_A) / NBLK;

    const uint32_t sbase = smem_u32(sm);
    const uint32_t wsm = sbase;
    const uint32_t bsm = sbase + BT_OFF;
    float* s_b = (float*)((char*)sm + BIAS_OFF);

    // prologue: wmDual -> smem (row stride WROW), bias
    {
        const uint32_t* src = (const uint32_t*)g_wmDual;   // 8192 u32
        #pragma unroll
        for (int it = 0; it < 32; it++) {
            int idx = it * 256 + tid;
            int row = idx >> 7, col2 = idx & 127;
            uint32_t v = src[idx];
            asm volatile("st.shared.b32 [%0], %1;"
                         :: "r"(wsm + (uint32_t)(row * (WROW / 2) + col2) * 4), "r"(v));
        }
        if (tid < 64) s_b[tid] = g_bias[tid];
    }

    const int cc = tid >> 2;
    const int lseg = (tid & 3) * 32;
    const uint32_t hi_addr = bsm + (uint32_t)(cc * ROWB + lseg) * 2;
    const uint32_t lo_addr = hi_addr + (uint32_t)(64 * ROWB) * 2;
    const float* Xrow = X + (size_t)cc * Lc + lseg;

    const int m0 = (w & 3) * 16;
    const int n0 = (w >> 2) * 64;
    const int frow = (lane & 7) + ((lane >> 3) & 1) * 8;
    const int fcol8 = (lane >> 4) * 8;
    const uint32_t a_base = wsm + (uint32_t)((m0 + frow) * WROW + fcol8) * 2;
    const uint32_t b_base = bsm + (uint32_t)(frow * ROWB + n0 + fcol8) * 2;

    float4 xv[8];
    {   // prefetch tile ts
        const float* p = Xrow + (size_t)(ts >> 6) * (Cc * Lc) + ((ts & 63) << 7);
        #pragma unroll
        for (int j = 0; j < 8; j++) xv[j] = *(const float4*)&p[j * 4];
    }
    __syncthreads();

    #pragma unroll 1
    for (int i = ts; i < te; i++) {
        const int bb = i >> 6, l0 = (i & 63) << 7;

        // ---- convert regs -> stacked bf16 B ----
        #pragma unroll
        for (int j = 0; j < 8; j++)
            split_store(hi_addr + j * 8, lo_addr + j * 8, xv[j]);
        __syncthreads();

        // ---- prefetch tile i+1 (hides under mma) ----
        if (i + 1 < te) {
            const float* p = Xrow + (size_t)((i + 1) >> 6) * (Cc * Lc)
                             + (((i + 1) & 63) << 7);
            #pragma unroll
            for (int j = 0; j < 8; j++) xv[j] = *(const float4*)&p[j * 4];
        }

        // ---- HMMA: 8 phys k-steps x (4 B-ldsm + 2 A-ldsm + 16 mma) ----
        float acc[8][4];
        #pragma unroll
        for (int t = 0; t < 8; t++) { acc[t][0] = acc[t][1] = acc[t][2] = acc[t][3] = 0.f; }

        #pragma unroll
        for (int kp = 0; kp < 8; kp++) {
            uint32_t bq[8][2];
            #pragma unroll
            for (int nb = 0; nb < 4; nb++) {
                uint32_t b0, b1, b2, b3;
                ldsm_x4t(b_base + (uint32_t)(kp * 16 * ROWB + nb * 16) * 2,
                         b0, b1, b2, b3);
                bq[2 * nb][0] = b0; bq[2 * nb][1] = b1;
                bq[2 * nb + 1][0] = b2; bq[2 * nb + 1][1] = b3;
            }
            uint32_t a0, a1, a2, a3, c0, c1, c2, c3;
            ldsm_x4(a_base + (uint32_t)(kp * 16) * 2, a0, a1, a2, a3);
            ldsm_x4(a_base + (uint32_t)(128 + kp * 16) * 2, c0, c1, c2, c3);
            #pragma unroll
            for (int j = 0; j < 8; j++) {
                mma16816(acc[j], a0, a1, a2, a3, bq[j][0], bq[j][1]);
                mma16816(acc[j], c0, c1, c2, c3, bq[j][0], bq[j][1]);
            }
        }

        // ---- epilogue: Y fragments - bias (registers only) ----
        {
            const int r0 = m0 + (lane >> 2);
            const float bb0 = s_b[r0], bb1 = s_b[r0 + 8];
            float* Yb = Y + (size_t)bb * (Cc * Lc) + l0 + n0 + 2 * (lane & 3);
            float* y0 = Yb + (size_t)r0 * Lc;
            float* y1 = Yb + (size_t)(r0 + 8) * Lc;
            #pragma unroll
            for (int j = 0; j < 8; j++) {
                *(float2*)&y0[j * 8] = make_float2(acc[j][0] - bb0, acc[j][1] - bb0);
                *(float2*)&y1[j * 8] = make_float2(acc[j][2] - bb1, acc[j][3] - bb1);
            }
        }
        __syncthreads();   // B smem fully consumed before next convert
    }
}

// ================= launch =================
extern "C" void kernel_launch(void* const* d_in, const int* in_sizes, int n_in,
                              void* d_out, int out_size) {
    const float* X = (const float*)d_in[0];
    float* Y = (float*)d_out;

    cudaFuncSetAttribute(gram_kernel, cudaFuncAttributeMaxDynamicSharedMemorySize,
                         SMEM_G);
    cudaFuncSetAttribute(apply_kernel, cudaFuncAttributeMaxDynamicSharedMemorySize,
                         SMEM_A2);
    cudaFuncSetAttribute(solver_kernel, cudaFuncAttributeMaxDynamicSharedMemorySize,
                         SOLVER_SMEM);

    gram_kernel<<<NBLK, 256, SMEM_G>>>(X);
    reduce_kernel<<<129, 256>>>();
    solver_kernel<<<1, 256, SOLVER_SMEM>>>();
    apply_kernel<<<NBLK, 256, SMEM_A2>>>(X, Y);
}

// round 16
// speedup vs baseline: 1.0759x; 1.0759x over previous
#include <cuda_runtime.h>
#include <cuda_bf16.h>
#include <cstdint>

#define Bb 32
#define Cc 64
#define Lc 8192
#define Mm (Bb * Lc)
#define NBLK 296                 // 148 SMs x 2 resident blocks
#define NT_G 2048                // gram tiles (128 cols each)
#define NT_A 2048                // apply tiles (128 cols each)
#define GPAD 132                 // fp32 stage row stride (floats)
#define ROWB 136                 // bf16 tile row stride (elements) -> 272 B
#define WROW 264                 // wmDual smem row stride (bf16 elements)
#define EPSV 1e-5f

__device__ __align__(16) float g_gram_part[NBLK * 4096];
__device__ __align__(16) float g_sum_part[NBLK * 64];
__device__ __align__(16) float g_gram[4096];
__device__ __align__(16) float g_mean[64];
__device__ __align__(16) __nv_bfloat16 g_wmDual[64 * 256];   // [c][ wh | wl | wl | wh ]
__device__ __align__(16) float g_bias[64];

// ---------------- f32x2 / smem helpers ----------------
__device__ __forceinline__ unsigned long long dup2(float v) {
    unsigned long long r; asm("mov.b64 %0, {%1, %1};" : "=l"(r) : "f"(v)); return r;
}
__device__ __forceinline__ void fma2(unsigned long long& d, unsigned long long a,
                                     unsigned long long b) {
    asm("fma.rn.f32x2 %0, %1, %2, %0;" : "+l"(d) : "l"(a), "l"(b));
}
__device__ __forceinline__ float2 unpk(unsigned long long v) {
    float2 r; asm("mov.b64 {%0, %1}, %2;" : "=f"(r.x), "=f"(r.y) : "l"(v)); return r;
}
__device__ __forceinline__ uint32_t smem_u32(const void* p) {
    uint32_t a;
    asm("{ .reg .u64 t; cvta.to.shared.u64 t, %1; cvt.u32.u64 %0, t; }" : "=r"(a) : "l"(p));
    return a;
}
__device__ __forceinline__ void cpasync16(uint32_t dst, const float* src) {
    asm volatile("cp.async.cg.shared.global [%0], [%1], 16;" :: "r"(dst), "l"(src));
}
#define CP_COMMIT() asm volatile("cp.async.commit_group;" ::: "memory")
#define CP_WAIT(n)  asm volatile("cp.async.wait_group %0;" :: "n"(n) : "memory")

// ---------------- mma.sync helpers (baseline PTX, sm_80+) ----------------
__device__ __forceinline__ void ldsm_x4(uint32_t addr, uint32_t& r0, uint32_t& r1,
                                        uint32_t& r2, uint32_t& r3) {
    asm volatile("ldmatrix.sync.aligned.m8n8.x4.shared.b16 {%0,%1,%2,%3}, [%4];"
                 : "=r"(r0), "=r"(r1), "=r"(r2), "=r"(r3) : "r"(addr));
}
__device__ __forceinline__ void ldsm_x4t(uint32_t addr, uint32_t& r0, uint32_t& r1,
                                         uint32_t& r2, uint32_t& r3) {
    asm volatile("ldmatrix.sync.aligned.m8n8.x4.trans.shared.b16 {%0,%1,%2,%3}, [%4];"
                 : "=r"(r0), "=r"(r1), "=r"(r2), "=r"(r3) : "r"(addr));
}
__device__ __forceinline__ void mma16816(float* d, uint32_t a0, uint32_t a1,
                                         uint32_t a2, uint32_t a3,
                                         uint32_t b0, uint32_t b1) {
    asm volatile(
        "mma.sync.aligned.m16n8k16.row.col.f32.bf16.bf16.f32 "
        "{%0,%1,%2,%3}, {%4,%5,%6,%7}, {%8,%9}, {%0,%1,%2,%3};"
        : "+f"(d[0]), "+f"(d[1]), "+f"(d[2]), "+f"(d[3])
        : "r"(a0), "r"(a1), "r"(a2), "r"(a3), "r"(b0), "r"(b1));
}
__device__ __forceinline__ uint32_t bfpack(float lo, float hi) {
    uint32_t r; asm("cvt.rn.bf16x2.f32 %0, %2, %1;" : "=r"(r) : "f"(lo), "f"(hi));
    return r;
}
__device__ __forceinline__ void sts64(uint32_t a, uint32_t v0, uint32_t v1) {
    asm volatile("st.shared.v2.b32 [%0], {%1, %2};" :: "r"(a), "r"(v0), "r"(v1));
}
__device__ __forceinline__ void split_store(uint32_t hi_a, uint32_t lo_a, float4 v) {
    uint32_t h0 = bfpack(v.x, v.y);
    uint32_t h1 = bfpack(v.z, v.w);
    float r0 = v.x - __uint_as_float(h0 << 16);
    float r1 = v.y - __uint_as_float(h0 & 0xffff0000u);
    float r2 = v.z - __uint_as_float(h1 << 16);
    float r3 = v.w - __uint_as_float(h1 & 0xffff0000u);
    sts64(hi_a, h0, h1);
    sts64(lo_a, bfpack(r0, r1), bfpack(r2, r3));
}

// ================= Kernel 1: Gram via mma.sync, DOUBLE-BUFFERED stage ==============
// smem: fp32 stage0 @0 (33792 B), stage1 @33792, bf16 B tile [128][ROWB] @67584
// (34816 B). Total 102400 -> occ 2. Tile i+1's cp.async group is issued BEFORE
// tile i's mma and drained with CP_WAIT(1) at the top of iteration i+1, so the
// DRAM latency hides under a full convert+mma phase (round-14's CP_WAIT(0)
// blocked every tile). Epilogue D [128][132] fp32 overlays the dead stages.
#define ST_STRIDE 8448           // stage stride in floats (33792 B)
#define BF_OFF 67584
#define SMEM_G 102400

__global__ __launch_bounds__(256) void gram_kernel(const float* __restrict__ X) {
    extern __shared__ float gsm[];
    const int tid = threadIdx.x;
    const int lane = tid & 31, w = tid >> 5;
    const int bid = blockIdx.x;
    const int ts = (bid * NT_G) / NBLK;
    const int te = ((bid + 1) * NT_G) / NBLK;

    const uint32_t sbase = smem_u32(gsm);
    const uint32_t bfbase = sbase + BF_OFF;

    const int cc = tid >> 2;
    const int lseg = (tid & 3) * 32;
    const uint32_t hi_addr = bfbase + (uint32_t)(cc * ROWB + lseg) * 2;
    const uint32_t lo_addr = hi_addr + (uint32_t)(64 * ROWB) * 2;

    const int m0 = w * 16;
    const int arow = m0 + (lane & 7) + ((lane >> 3) & 1) * 8;
    const int acol = (lane >> 4) * 8;
    const uint32_t a_addr = bfbase + (uint32_t)(arow * ROWB + acol) * 2;
    const int brow = (lane & 7) + (lane >> 4) * 8;
    const int bcol = ((lane >> 3) & 1) * 8;
    const uint32_t b_addr = bfbase + (uint32_t)(brow * ROWB + bcol) * 2;

    float acc[16][4];
    #pragma unroll
    for (int t = 0; t < 16; t++) { acc[t][0] = acc[t][1] = acc[t][2] = acc[t][3] = 0.f; }
    float csum = 0.f;

    // issue stage for tile ts into buffer 0
    {
        int bb = ts >> 6, l0 = (ts & 63) << 7;
        const float* Xb = X + (size_t)bb * (Cc * Lc) + l0;
        #pragma unroll
        for (int it = 0; it < 8; it++) {
            int p = it * 256 + tid, c2 = p >> 5, l4 = p & 31;
            cpasync16(sbase + (uint32_t)(c2 * GPAD + l4 * 4) * 4,
                      Xb + (size_t)c2 * Lc + l4 * 4);
        }
        CP_COMMIT();
    }

    #pragma unroll 1
    for (int i = ts; i < te; i++) {
        const int cur = (i - ts) & 1;
        // issue stage for tile i+1 into the other buffer, then drain tile i's group
        if (i + 1 < te) {
            int bb = (i + 1) >> 6, l0 = ((i + 1) & 63) << 7;
            const float* Xb = X + (size_t)bb * (Cc * Lc) + l0;
            const uint32_t dst = sbase + (uint32_t)((1 - cur) * ST_STRIDE) * 4;
            #pragma unroll
            for (int it = 0; it < 8; it++) {
                int p = it * 256 + tid, c2 = p >> 5, l4 = p & 31;
                cpasync16(dst + (uint32_t)(c2 * GPAD + l4 * 4) * 4,
                          Xb + (size_t)c2 * Lc + l4 * 4);
            }
            CP_COMMIT();
            CP_WAIT(1);          // tile i staged; tile i+1 in flight under mma below
        } else {
            CP_WAIT(0);
        }
        __syncthreads();

        // ---- convert stage[cur] -> stacked bf16 tile (+ channel sums) ----
        {
            const float* srow = gsm + cur * ST_STRIDE + cc * GPAD + lseg;
            float s0 = 0.f, s1 = 0.f, s2 = 0.f, s3 = 0.f;
            #pragma unroll
            for (int j = 0; j < 8; j++) {
                float4 v = *(const float4*)&srow[j * 4];
                s0 += v.x; s1 += v.y; s2 += v.z; s3 += v.w;
                split_store(hi_addr + j * 8, lo_addr + j * 8, v);
            }
            csum += (s0 + s1) + (s2 + s3);
        }
        __syncthreads();

        // ---- HMMA: warp w computes D rows m0..m0+15, all 128 cols ----
        #pragma unroll
        for (int ks = 0; ks < 8; ks++) {
            const uint32_t koff = (uint32_t)(ks * 32);
            uint32_t a0, a1, a2, a3;
            ldsm_x4(a_addr + koff, a0, a1, a2, a3);
            #pragma unroll
            for (int nb = 0; nb < 8; nb++) {
                uint32_t b0, b1, b2, b3;
                ldsm_x4(b_addr + (uint32_t)(nb * 16 * ROWB * 2) + koff, b0, b1, b2, b3);
                mma16816(acc[2 * nb], a0, a1, a2, a3, b0, b1);
                mma16816(acc[2 * nb + 1], a0, a1, a2, a3, b2, b3);
            }
        }
        __syncthreads();    // B tile fully consumed before next convert overwrites
    }

    // ---- epilogue: D -> smem (overlays stages), fold quadrants ----
    float* Dsm = gsm;
    {
        const int row_in = lane >> 2, kq = lane & 3;
        #pragma unroll
        for (int nt = 0; nt < 16; nt++) {
            float* dr = Dsm + (m0 + row_in) * 132 + nt * 8 + 2 * kq;
            dr[0] = acc[nt][0];
            dr[1] = acc[nt][1];
            dr[132 * 8] = acc[nt][2];
            dr[132 * 8 + 1] = acc[nt][3];
        }
    }
    __syncthreads();
    {
        float* gp = g_gram_part + (size_t)bid * 4096;
        for (int e = tid; e < 4096; e += 256) {
            int c1 = e >> 6, c2 = e & 63;
            gp[e] = (Dsm[c1 * 132 + c2] + Dsm[c1 * 132 + c2 + 64])
                  + (Dsm[(c1 + 64) * 132 + c2] + Dsm[(c1 + 64) * 132 + c2 + 64]);
        }
    }
    csum += __shfl_down_sync(0xffffffffu, csum, 2, 4);
    csum += __shfl_down_sync(0xffffffffu, csum, 1, 4);
    if ((tid & 3) == 0) g_sum_part[bid * 64 + (tid >> 2)] = csum;
}

// ================= Kernel 2: reduction (unchanged) =================
__global__ __launch_bounds__(256) void reduce_kernel() {
    __shared__ float s[256];
    const int tid = threadIdx.x;
    if (blockIdx.x < 128) {
        const int e = blockIdx.x * 32 + (tid & 31);
        const int ch = tid >> 5;
        const float* base = g_gram_part + (size_t)(ch * 37) * 4096 + e;
        float a0 = 0, a1 = 0, a2 = 0, a3 = 0;
        #pragma unroll 1
        for (int q = 0; q < 36; q += 4) {
            a0 += base[(size_t)(q + 0) * 4096];
            a1 += base[(size_t)(q + 1) * 4096];
            a2 += base[(size_t)(q + 2) * 4096];
            a3 += base[(size_t)(q + 3) * 4096];
        }
        a0 += base[(size_t)36 * 4096];
        s[tid] = (a0 + a1) + (a2 + a3);
        __syncthreads();
        if (tid < 32) {
            float r = 0.f;
            #pragma unroll
            for (int c2 = 0; c2 < 8; c2++) r += s[c2 * 32 + tid];
            g_gram[blockIdx.x * 32 + tid] = r;
        }
    } else {
        const int c = tid & 63, ch = tid >> 6;
        const float* base = g_sum_part + (size_t)(ch * 74) * 64 + c;
        float a0 = 0, a1 = 0;
        #pragma unroll 1
        for (int q = 0; q < 74; q += 2) {
            a0 += base[(q + 0) * 64];
            a1 += base[(q + 1) * 64];
        }
        s[tid] = a0 + a1;
        __syncthreads();
        if (tid < 64) {
            float r = (s[tid] + s[64 + tid]) + (s[128 + tid] + s[192 + tid]);
            g_mean[tid] = r * (1.0f / (float)Mm);
        }
    }
}

// ================= Kernel 3: Sigma + Newton-Schulz (+ wmDual emit) =================
#define SOLVER_SMEM (4 * 4096 * (int)sizeof(float))

__global__ __launch_bounds__(256) void solver_kernel() {
    extern __shared__ float ssm[];
    float* P = ssm;
    float* S = ssm + 4096;
    float* U = ssm + 8192;
    float* V = ssm + 12288;
    const int tid = threadIdx.x;
    const float inv_m = 1.0f / (float)Mm;

    for (int e = tid; e < 4096; e += 256) {
        int c1 = e >> 6, c2 = e & 63;
        S[e] = g_gram[e] * inv_m - g_mean[c1] * g_mean[c2] + ((c1 == c2) ? EPSV : 0.0f);
    }
    __syncthreads();
    float tr = 0.f;
    #pragma unroll
    for (int c = 0; c < 64; c++) tr += S[c * 65];
    const float rTr = 1.0f / tr;
    __syncthreads();
    for (int e = tid; e < 4096; e += 256) {
        S[e] *= rTr;
        int c1 = e >> 6, c2 = e & 63;
        P[e] = (c1 == c2) ? 1.0f : 0.0f;
    }
    __syncthreads();

    const int ty = tid >> 4, tx = tid & 15;
    const int r = ty * 4, cb = tx * 4;

    #pragma unroll 1
    for (int it = 0; it < 5; it++) {
        unsigned long long aU[4][2] = {}, aV[4][2] = {};
        #pragma unroll
        for (int k4 = 0; k4 < 16; k4++) {
            float4 a0 = *(const float4*)&P[(r + 0) * 64 + k4 * 4];
            float4 a1 = *(const float4*)&P[(r + 1) * 64 + k4 * 4];
            float4 a2 = *(const float4*)&P[(r + 2) * 64 + k4 * 4];
            float4 a3 = *(const float4*)&P[(r + 3) * 64 + k4 * 4];
            #pragma unroll
            for (int kk = 0; kk < 4; kk++) {
                float f0 = kk == 0 ? a0.x : kk == 1 ? a0.y : kk == 2 ? a0.z : a0.w;
                float f1 = kk == 0 ? a1.x : kk == 1 ? a1.y : kk == 2 ? a1.z : a1.w;
                float f2 = kk == 0 ? a2.x : kk == 1 ? a2.y : kk == 2 ? a2.z : a2.w;
                float f3 = kk == 0 ? a3.x : kk == 1 ? a3.y : kk == 2 ? a3.z : a3.w;
                const int k = k4 * 4 + kk;
                ulonglong2 bp = *(const ulonglong2*)&P[k * 64 + cb];
                ulonglong2 bs = *(const ulonglong2*)&S[k * 64 + cb];
                unsigned long long d;
                d = dup2(f0);
                fma2(aU[0][0], d, bp.x); fma2(aU[0][1], d, bp.y);
                fma2(aV[0][0], d, bs.x); fma2(aV[0][1], d, bs.y);
                d = dup2(f1);
                fma2(aU[1][0], d, bp.x); fma2(aU[1][1], d, bp.y);
                fma2(aV[1][0], d, bs.x); fma2(aV[1][1], d, bs.y);
                d = dup2(f2);
                fma2(aU[2][0], d, bp.x); fma2(aU[2][1], d, bp.y);
                fma2(aV[2][0], d, bs.x); fma2(aV[2][1], d, bs.y);
                d = dup2(f3);
                fma2(aU[3][0], d, bp.x); fma2(aU[3][1], d, bp.y);
                fma2(aV[3][0], d, bs.x); fma2(aV[3][1], d, bs.y);
            }
        }
        #pragma unroll
        for (int i = 0; i < 4; i++) {
            float2 u0 = unpk(aU[i][0]), u1 = unpk(aU[i][1]);
            float2 v0 = unpk(aV[i][0]), v1 = unpk(aV[i][1]);
            *(float4*)&U[(r + i) * 64 + cb] = make_float4(u0.x, u0.y, u1.x, u1.y);
            *(float4*)&V[(r + i) * 64 + cb] = make_float4(v0.x, v0.y, v1.x, v1.y);
        }
        __syncthreads();

        unsigned long long aW[4][2] = {};
        #pragma unroll
        for (int k4 = 0; k4 < 16; k4++) {
            float4 a0 = *(const float4*)&U[(r + 0) * 64 + k4 * 4];
            float4 a1 = *(const float4*)&U[(r + 1) * 64 + k4 * 4];
            float4 a2 = *(const float4*)&U[(r + 2) * 64 + k4 * 4];
            float4 a3 = *(const float4*)&U[(r + 3) * 64 + k4 * 4];
            #pragma unroll
            for (int kk = 0; kk < 4; kk++) {
                float f0 = kk == 0 ? a0.x : kk == 1 ? a0.y : kk == 2 ? a0.z : a0.w;
                float f1 = kk == 0 ? a1.x : kk == 1 ? a1.y : kk == 2 ? a1.z : a1.w;
                float f2 = kk == 0 ? a2.x : kk == 1 ? a2.y : kk == 2 ? a2.z : a2.w;
                float f3 = kk == 0 ? a3.x : kk == 1 ? a3.y : kk == 2 ? a3.z : a3.w;
                ulonglong2 bv = *(const ulonglong2*)&V[(k4 * 4 + kk) * 64 + cb];
                unsigned long long d;
                d = dup2(f0); fma2(aW[0][0], d, bv.x); fma2(aW[0][1], d, bv.y);
                d = dup2(f1); fma2(aW[1][0], d, bv.x); fma2(aW[1][1], d, bv.y);
                d = dup2(f2); fma2(aW[2][0], d, bv.x); fma2(aW[2][1], d, bv.y);
                d = dup2(f3); fma2(aW[3][0], d, bv.x); fma2(aW[3][1], d, bv.y);
            }
        }
        #pragma unroll
        for (int i = 0; i < 4; i++) {
            float2 w0 = unpk(aW[i][0]), w1 = unpk(aW[i][1]);
            float* pr = &P[(r + i) * 64 + cb];
            float4 pv = *(float4*)pr;
            *(float4*)pr = make_float4(1.5f * pv.x - 0.5f * w0.x,
                                       1.5f * pv.y - 0.5f * w0.y,
                                       1.5f * pv.z - 0.5f * w1.x,
                                       1.5f * pv.w - 0.5f * w1.y);
        }
        __syncthreads();
    }

    const float sq = sqrtf(rTr);
    for (int e = tid; e < 4096; e += 256) {
        int c = e >> 6, k = e & 63;
        float wv = P[c * 64 + k] * sq;
        __nv_bfloat16 h = __float2bfloat16(wv);
        __nv_bfloat16 l = __float2bfloat16(wv - __bfloat162float(h));
        g_wmDual[c * 256 + k] = h;
        g_wmDual[c * 256 + 64 + k] = l;
        g_wmDual[c * 256 + 128 + k] = l;
        g_wmDual[c * 256 + 192 + k] = h;
    }
    if (tid < 64) {
        float bs = 0.f;
        #pragma unroll 8
        for (int cp = 0; cp < 64; cp++) bs += P[tid * 64 + cp] * g_mean[cp];
        g_bias[tid] = bs * sq;
    }
}

// ================= Kernel 4: apply via mma.sync dual-stack (round-14, 43.9us) =======
#define WS_OFF 33792
#define BT_OFF 67584
#define BIAS_OFF 102400
#define SMEM_A2 102656

__global__ __launch_bounds__(256) void apply_kernel(const float* __restrict__ X,
                                                    float* __restrict__ Y) {
    extern __shared__ float sm[];
    const int tid = threadIdx.x;
    const int lane = tid & 31, w = tid >> 5;
    const int bid = blockIdx.x;
    const int ts = (bid * NT_A) / NBLK;
    const int te = ((bid + 1) * NT_A) / NBLK;

    const uint32_t sbase = smem_u32(sm);
    const uint32_t wsm = sbase + WS_OFF;
    const uint32_t bsm = sbase + BT_OFF;
    float* s_b = (float*)((char*)sm + BIAS_OFF);

    {
        const uint32_t* src = (const uint32_t*)g_wmDual;   // 8192 u32
        #pragma unroll
        for (int it = 0; it < 32; it++) {
            int idx = it * 256 + tid;
            int row = idx >> 7, col2 = idx & 127;
            uint32_t v = src[idx];
            asm volatile("st.shared.b32 [%0], %1;"
                         :: "r"(wsm + (uint32_t)(row * (WROW / 2) + col2) * 4), "r"(v));
        }
        if (tid < 64) s_b[tid] = g_bias[tid];
    }

    const int cc = tid >> 2;
    const int lseg = (tid & 3) * 32;
    const uint32_t hi_addr = bsm + (uint32_t)(cc * ROWB + lseg) * 2;
    const uint32_t lo_addr = hi_addr + (uint32_t)(64 * ROWB) * 2;

    const int m0 = (w & 3) * 16;
    const int n0 = (w >> 2) * 64;
    const int frow = (lane & 7) + ((lane >> 3) & 1) * 8;
    const int fcol8 = (lane >> 4) * 8;
    const uint32_t a_base = wsm + (uint32_t)((m0 + frow) * WROW + fcol8) * 2;
    const uint32_t b_base = bsm + (uint32_t)(frow * ROWB + n0 + fcol8) * 2;

    __syncthreads();

    #pragma unroll 1
    for (int i = ts; i < te; i++) {
        const int bb = i >> 6, l0 = (i & 63) << 7;
        {
            const float* Xb = X + (size_t)bb * (Cc * Lc) + l0;
            #pragma unroll
            for (int it = 0; it < 8; it++) {
                int p = it * 256 + tid, c2 = p >> 5, l4 = p & 31;
                cpasync16(sbase + (uint32_t)(c2 * GPAD + l4 * 4) * 4,
                          Xb + (size_t)c2 * Lc + l4 * 4);
            }
            CP_COMMIT(); CP_WAIT(0);
        }
        __syncthreads();

        {
            const float* srow = sm + cc * GPAD + lseg;
            #pragma unroll
            for (int j = 0; j < 8; j++) {
                float4 v = *(const float4*)&srow[j * 4];
                split_store(hi_addr + j * 8, lo_addr + j * 8, v);
            }
        }
        __syncthreads();

        float acc[8][4];
        #pragma unroll
        for (int t = 0; t < 8; t++) { acc[t][0] = acc[t][1] = acc[t][2] = acc[t][3] = 0.f; }

        #pragma unroll
        for (int kp = 0; kp < 8; kp++) {
            uint32_t bq[8][2];
            #pragma unroll
            for (int nb = 0; nb < 4; nb++) {
                uint32_t b0, b1, b2, b3;
                ldsm_x4t(b_base + (uint32_t)(kp * 16 * ROWB + nb * 16) * 2,
                         b0, b1, b2, b3);
                bq[2 * nb][0] = b0; bq[2 * nb][1] = b1;
                bq[2 * nb + 1][0] = b2; bq[2 * nb + 1][1] = b3;
            }
            uint32_t a0, a1, a2, a3, c0, c1, c2, c3;
            ldsm_x4(a_base + (uint32_t)(kp * 16) * 2, a0, a1, a2, a3);
            ldsm_x4(a_base + (uint32_t)(128 + kp * 16) * 2, c0, c1, c2, c3);
            #pragma unroll
            for (int j = 0; j < 8; j++) {
                mma16816(acc[j], a0, a1, a2, a3, bq[j][0], bq[j][1]);
                mma16816(acc[j], c0, c1, c2, c3, bq[j][0], bq[j][1]);
            }
        }

        {
            const int r0 = m0 + (lane >> 2);
            const float bb0 = s_b[r0], bb1 = s_b[r0 + 8];
            float* Yb = Y + (size_t)bb * (Cc * Lc) + l0 + n0 + 2 * (lane & 3);
            float* y0 = Yb + (size_t)r0 * Lc;
            float* y1 = Yb + (size_t)(r0 + 8) * Lc;
            #pragma unroll
            for (int j = 0; j < 8; j++) {
                *(float2*)&y0[j * 8] = make_float2(acc[j][0] - bb0, acc[j][1] - bb0);
                *(float2*)&y1[j * 8] = make_float2(acc[j][2] - bb1, acc[j][3] - bb1);
            }
        }
        __syncthreads();
    }
}

// ================= launch =================
extern "C" void kernel_launch(void* const* d_in, const int* in_sizes, int n_in,
                              void* d_out, int out_size) {
    const float* X = (const float*)d_in[0];
    float* Y = (float*)d_out;

    cudaFuncSetAttribute(gram_kernel, cudaFuncAttributeMaxDynamicSharedMemorySize,
                         SMEM_G);
    cudaFuncSetAttribute(apply_kernel, cudaFuncAttributeMaxDynamicSharedMemorySize,
                         SMEM_A2);
    cudaFuncSetAttribute(solver_kernel, cudaFuncAttributeMaxDynamicSharedMemorySize,
                         SOLVER_SMEM);

    gram_kernel<<<NBLK, 256, SMEM_G>>>(X);
    reduce_kernel<<<129, 256>>>();
    solver_kernel<<<1, 256, SOLVER_SMEM>>>();
    apply_kernel<<<NBLK, 256, SMEM_A2>>>(X, Y);
}

// round 17
// speedup vs baseline: 1.1057x; 1.0278x over previous
#include <cuda_runtime.h>
#include <cuda_bf16.h>
#include <cstdint>

#define Bb 32
#define Cc 64
#define Lc 8192
#define Mm (Bb * Lc)
#define NBLK 296                 // 148 SMs x 2 resident blocks
#define NT_G 2048                // gram tiles (128 cols each)
#define NT_A 2048                // apply tiles (128 cols each)
#define GPAD 132                 // fp32 stage row stride (floats)
#define ROWB 136                 // bf16 tile row stride (elements) -> 272 B
#define WROW 264                 // wmDual smem row stride (bf16 elements)
#define EPSV 1e-5f

__device__ __align__(16) float g_gram_part[NBLK * 4096];
__device__ __align__(16) float g_sum_part[NBLK * 64];
__device__ __align__(16) float g_gram[4096];
__device__ __align__(16) float g_mean[64];
__device__ __align__(16) __nv_bfloat16 g_wmDual[64 * 256];   // [c][ wh | wl | wl | wh ]
__device__ __align__(16) float g_bias[64];

// ---------------- f32x2 / smem helpers ----------------
__device__ __forceinline__ unsigned long long dup2(float v) {
    unsigned long long r; asm("mov.b64 %0, {%1, %1};" : "=l"(r) : "f"(v)); return r;
}
__device__ __forceinline__ void fma2(unsigned long long& d, unsigned long long a,
                                     unsigned long long b) {
    asm("fma.rn.f32x2 %0, %1, %2, %0;" : "+l"(d) : "l"(a), "l"(b));
}
__device__ __forceinline__ float2 unpk(unsigned long long v) {
    float2 r; asm("mov.b64 {%0, %1}, %2;" : "=f"(r.x), "=f"(r.y) : "l"(v)); return r;
}
__device__ __forceinline__ uint32_t smem_u32(const void* p) {
    uint32_t a;
    asm("{ .reg .u64 t; cvta.to.shared.u64 t, %1; cvt.u32.u64 %0, t; }" : "=r"(a) : "l"(p));
    return a;
}
__device__ __forceinline__ void cpasync16(uint32_t dst, const float* src) {
    asm volatile("cp.async.cg.shared.global [%0], [%1], 16;" :: "r"(dst), "l"(src));
}
#define CP_COMMIT() asm volatile("cp.async.commit_group;" ::: "memory")
#define CP_WAIT(n)  asm volatile("cp.async.wait_group %0;" :: "n"(n) : "memory")

// ---------------- mma.sync helpers (baseline PTX, sm_80+) ----------------
__device__ __forceinline__ void ldsm_x4(uint32_t addr, uint32_t& r0, uint32_t& r1,
                                        uint32_t& r2, uint32_t& r3) {
    asm volatile("ldmatrix.sync.aligned.m8n8.x4.shared.b16 {%0,%1,%2,%3}, [%4];"
                 : "=r"(r0), "=r"(r1), "=r"(r2), "=r"(r3) : "r"(addr));
}
__device__ __forceinline__ void ldsm_x4t(uint32_t addr, uint32_t& r0, uint32_t& r1,
                                         uint32_t& r2, uint32_t& r3) {
    asm volatile("ldmatrix.sync.aligned.m8n8.x4.trans.shared.b16 {%0,%1,%2,%3}, [%4];"
                 : "=r"(r0), "=r"(r1), "=r"(r2), "=r"(r3) : "r"(addr));
}
__device__ __forceinline__ void mma16816(float* d, uint32_t a0, uint32_t a1,
                                         uint32_t a2, uint32_t a3,
                                         uint32_t b0, uint32_t b1) {
    asm volatile(
        "mma.sync.aligned.m16n8k16.row.col.f32.bf16.bf16.f32 "
        "{%0,%1,%2,%3}, {%4,%5,%6,%7}, {%8,%9}, {%0,%1,%2,%3};"
        : "+f"(d[0]), "+f"(d[1]), "+f"(d[2]), "+f"(d[3])
        : "r"(a0), "r"(a1), "r"(a2), "r"(a3), "r"(b0), "r"(b1));
}
__device__ __forceinline__ uint32_t bfpack(float lo, float hi) {
    uint32_t r; asm("cvt.rn.bf16x2.f32 %0, %2, %1;" : "=r"(r) : "f"(lo), "f"(hi));
    return r;
}
__device__ __forceinline__ void sts64(uint32_t a, uint32_t v0, uint32_t v1) {
    asm volatile("st.shared.v2.b32 [%0], {%1, %2};" :: "r"(a), "r"(v0), "r"(v1));
}
__device__ __forceinline__ void split_store(uint32_t hi_a, uint32_t lo_a, float4 v) {
    uint32_t h0 = bfpack(v.x, v.y);
    uint32_t h1 = bfpack(v.z, v.w);
    float r0 = v.x - __uint_as_float(h0 << 16);
    float r1 = v.y - __uint_as_float(h0 & 0xffff0000u);
    float r2 = v.z - __uint_as_float(h1 << 16);
    float r3 = v.w - __uint_as_float(h1 & 0xffff0000u);
    sts64(hi_a, h0, h1);
    sts64(lo_a, bfpack(r0, r1), bfpack(r2, r3));
}

// ================= Kernel 1: Gram via mma.sync =================
// Pipelined with ZERO-COST double buffering: per tile, wait(0) -> convert stage
// -> sync -> issue cp.async for tile i+1 into the SAME (now dead) stage -> mma.
// The DRAM latency of tile i+1 hides under tile i's mma phase.
// Warp tiles 32m x 64n (8 warps = 4m x 2n): 48 ldsm + 128 mma per warp per tile
// (-33% smem read traffic vs 16x128 tiles).
// smem: fp32 stage [64][GPAD] @0 (33792 B); bf16 B [128][ROWB] @33792 (34816 B).
// Epilogue D [128][132] fp32 (67584 B) overlays both. Total 68608 -> occ 2 (regs).
#define BF_OFF 33792
#define SMEM_G 68608

__global__ __launch_bounds__(256) void gram_kernel(const float* __restrict__ X) {
    extern __shared__ float gsm[];
    const int tid = threadIdx.x;
    const int lane = tid & 31, w = tid >> 5;
    const int bid = blockIdx.x;
    const int ts = (bid * NT_G) / NBLK;
    const int te = ((bid + 1) * NT_G) / NBLK;

    const uint32_t sbase = smem_u32(gsm);
    const uint32_t bfbase = sbase + BF_OFF;

    // conversion mapping
    const int cc = tid >> 2;
    const int lseg = (tid & 3) * 32;
    const uint32_t hi_addr = bfbase + (uint32_t)(cc * ROWB + lseg) * 2;
    const uint32_t lo_addr = hi_addr + (uint32_t)(64 * ROWB) * 2;

    // mma mapping: warp w -> (mi = w&3: rows mi*32..+31, nj = w>>2: cols nj*64..+63)
    const int mi = w & 3, nj = w >> 2;
    const int frow = (lane & 7) + ((lane >> 3) & 1) * 8;   // validated x4 pattern
    const int fcol8 = (lane >> 4) * 8;
    const uint32_t a_addr0 = bfbase + (uint32_t)((mi * 32 + frow) * ROWB + fcol8) * 2;
    const uint32_t a_addr1 = a_addr0 + (uint32_t)(16 * ROWB) * 2;
    const int brow = (lane & 7) + (lane >> 4) * 8;
    const int bcol = ((lane >> 3) & 1) * 8;
    const uint32_t b_addr = bfbase + (uint32_t)((nj * 64 + brow) * ROWB + bcol) * 2;

    float acc[2][8][4];
    #pragma unroll
    for (int mf = 0; mf < 2; mf++)
        #pragma unroll
        for (int nf = 0; nf < 8; nf++)
            { acc[mf][nf][0] = acc[mf][nf][1] = acc[mf][nf][2] = acc[mf][nf][3] = 0.f; }
    float csum = 0.f;

    // prologue: issue stage for tile ts
    {
        int bb = ts >> 6, l0 = (ts & 63) << 7;
        const float* Xb = X + (size_t)bb * (Cc * Lc) + l0;
        #pragma unroll
        for (int it = 0; it < 8; it++) {
            int p = it * 256 + tid, c2 = p >> 5, l4 = p & 31;
            cpasync16(sbase + (uint32_t)(c2 * GPAD + l4 * 4) * 4,
                      Xb + (size_t)c2 * Lc + l4 * 4);
        }
        CP_COMMIT();
    }

    #pragma unroll 1
    for (int i = ts; i < te; i++) {
        CP_WAIT(0);
        __syncthreads();             // stage i visible to all; prior mma done with B

        // ---- convert stage -> stacked bf16 tile (+ channel sums) ----
        {
            const float* srow = gsm + cc * GPAD + lseg;
            float s0 = 0.f, s1 = 0.f, s2 = 0.f, s3 = 0.f;
            #pragma unroll
            for (int j = 0; j < 8; j++) {
                float4 v = *(const float4*)&srow[j * 4];
                s0 += v.x; s1 += v.y; s2 += v.z; s3 += v.w;
                split_store(hi_addr + j * 8, lo_addr + j * 8, v);
            }
            csum += (s0 + s1) + (s2 + s3);
        }
        __syncthreads();             // stage dead, B tile ready

        // ---- issue stage for tile i+1 (hides under mma) ----
        if (i + 1 < te) {
            int bb = (i + 1) >> 6, l0 = ((i + 1) & 63) << 7;
            const float* Xb = X + (size_t)bb * (Cc * Lc) + l0;
            #pragma unroll
            for (int it = 0; it < 8; it++) {
                int p = it * 256 + tid, c2 = p >> 5, l4 = p & 31;
                cpasync16(sbase + (uint32_t)(c2 * GPAD + l4 * 4) * 4,
                          Xb + (size_t)c2 * Lc + l4 * 4);
            }
            CP_COMMIT();
        }

        // ---- HMMA: 8 k-steps x (2 A-ldsm + 4 B-ldsm + 16 mma) ----
        #pragma unroll
        for (int ks = 0; ks < 8; ks++) {
            const uint32_t koff = (uint32_t)(ks * 32);
            uint32_t a0, a1, a2, a3, c0, c1, c2, c3;
            ldsm_x4(a_addr0 + koff, a0, a1, a2, a3);
            ldsm_x4(a_addr1 + koff, c0, c1, c2, c3);
            #pragma unroll
            for (int nb = 0; nb < 4; nb++) {
                uint32_t b0, b1, b2, b3;
                ldsm_x4(b_addr + (uint32_t)(nb * 16 * ROWB * 2) + koff, b0, b1, b2, b3);
                mma16816(acc[0][2 * nb],     a0, a1, a2, a3, b0, b1);
                mma16816(acc[0][2 * nb + 1], a0, a1, a2, a3, b2, b3);
                mma16816(acc[1][2 * nb],     c0, c1, c2, c3, b0, b1);
                mma16816(acc[1][2 * nb + 1], c0, c1, c2, c3, b2, b3);
            }
        }
        __syncthreads();             // B consumed before next convert overwrites
    }

    // ---- epilogue: D -> smem (overlays stage+B), fold quadrants ----
    float* Dsm = gsm;
    {
        const int row_in = lane >> 2, kq = lane & 3;
        #pragma unroll
        for (int mf = 0; mf < 2; mf++) {
            #pragma unroll
            for (int nf = 0; nf < 8; nf++) {
                float* dr = Dsm + (mi * 32 + mf * 16 + row_in) * 132
                            + nj * 64 + nf * 8 + 2 * kq;
                dr[0] = acc[mf][nf][0];
                dr[1] = acc[mf][nf][1];
                dr[132 * 8] = acc[mf][nf][2];
                dr[132 * 8 + 1] = acc[mf][nf][3];
            }
        }
    }
    __syncthreads();
    {
        float* gp = g_gram_part + (size_t)bid * 4096;
        for (int e = tid; e < 4096; e += 256) {
            int c1 = e >> 6, c2 = e & 63;
            gp[e] = (Dsm[c1 * 132 + c2] + Dsm[c1 * 132 + c2 + 64])
                  + (Dsm[(c1 + 64) * 132 + c2] + Dsm[(c1 + 64) * 132 + c2 + 64]);
        }
    }
    csum += __shfl_down_sync(0xffffffffu, csum, 2, 4);
    csum += __shfl_down_sync(0xffffffffu, csum, 1, 4);
    if ((tid & 3) == 0) g_sum_part[bid * 64 + (tid >> 2)] = csum;
}

// ================= Kernel 2: reduction (unchanged) =================
__global__ __launch_bounds__(256) void reduce_kernel() {
    __shared__ float s[256];
    const int tid = threadIdx.x;
    if (blockIdx.x < 128) {
        const int e = blockIdx.x * 32 + (tid & 31);
        const int ch = tid >> 5;
        const float* base = g_gram_part + (size_t)(ch * 37) * 4096 + e;
        float a0 = 0, a1 = 0, a2 = 0, a3 = 0;
        #pragma unroll 1
        for (int q = 0; q < 36; q += 4) {
            a0 += base[(size_t)(q + 0) * 4096];
            a1 += base[(size_t)(q + 1) * 4096];
            a2 += base[(size_t)(q + 2) * 4096];
            a3 += base[(size_t)(q + 3) * 4096];
        }
        a0 += base[(size_t)36 * 4096];
        s[tid] = (a0 + a1) + (a2 + a3);
        __syncthreads();
        if (tid < 32) {
            float r = 0.f;
            #pragma unroll
            for (int c2 = 0; c2 < 8; c2++) r += s[c2 * 32 + tid];
            g_gram[blockIdx.x * 32 + tid] = r;
        }
    } else {
        const int c = tid & 63, ch = tid >> 6;
        const float* base = g_sum_part + (size_t)(ch * 74) * 64 + c;
        float a0 = 0, a1 = 0;
        #pragma unroll 1
        for (int q = 0; q < 74; q += 2) {
            a0 += base[(q + 0) * 64];
            a1 += base[(q + 1) * 64];
        }
        s[tid] = a0 + a1;
        __syncthreads();
        if (tid < 64) {
            float r = (s[tid] + s[64 + tid]) + (s[128 + tid] + s[192 + tid]);
            g_mean[tid] = r * (1.0f / (float)Mm);
        }
    }
}

// ================= Kernel 3: Sigma + Newton-Schulz (+ wmDual emit) =================
#define SOLVER_SMEM (4 * 4096 * (int)sizeof(float))

__global__ __launch_bounds__(256) void solver_kernel() {
    extern __shared__ float ssm[];
    float* P = ssm;
    float* S = ssm + 4096;
    float* U = ssm + 8192;
    float* V = ssm + 12288;
    const int tid = threadIdx.x;
    const float inv_m = 1.0f / (float)Mm;

    for (int e = tid; e < 4096; e += 256) {
        int c1 = e >> 6, c2 = e & 63;
        S[e] = g_gram[e] * inv_m - g_mean[c1] * g_mean[c2] + ((c1 == c2) ? EPSV : 0.0f);
    }
    __syncthreads();
    float tr = 0.f;
    #pragma unroll
    for (int c = 0; c < 64; c++) tr += S[c * 65];
    const float rTr = 1.0f / tr;
    __syncthreads();
    for (int e = tid; e < 4096; e += 256) {
        S[e] *= rTr;
        int c1 = e >> 6, c2 = e & 63;
        P[e] = (c1 == c2) ? 1.0f : 0.0f;
    }
    __syncthreads();

    const int ty = tid >> 4, tx = tid & 15;
    const int r = ty * 4, cb = tx * 4;

    #pragma unroll 1
    for (int it = 0; it < 5; it++) {
        unsigned long long aU[4][2] = {}, aV[4][2] = {};
        #pragma unroll
        for (int k4 = 0; k4 < 16; k4++) {
            float4 a0 = *(const float4*)&P[(r + 0) * 64 + k4 * 4];
            float4 a1 = *(const float4*)&P[(r + 1) * 64 + k4 * 4];
            float4 a2 = *(const float4*)&P[(r + 2) * 64 + k4 * 4];
            float4 a3 = *(const float4*)&P[(r + 3) * 64 + k4 * 4];
            #pragma unroll
            for (int kk = 0; kk < 4; kk++) {
                float f0 = kk == 0 ? a0.x : kk == 1 ? a0.y : kk == 2 ? a0.z : a0.w;
                float f1 = kk == 0 ? a1.x : kk == 1 ? a1.y : kk == 2 ? a1.z : a1.w;
                float f2 = kk == 0 ? a2.x : kk == 1 ? a2.y : kk == 2 ? a2.z : a2.w;
                float f3 = kk == 0 ? a3.x : kk == 1 ? a3.y : kk == 2 ? a3.z : a3.w;
                const int k = k4 * 4 + kk;
                ulonglong2 bp = *(const ulonglong2*)&P[k * 64 + cb];
                ulonglong2 bs = *(const ulonglong2*)&S[k * 64 + cb];
                unsigned long long d;
                d = dup2(f0);
                fma2(aU[0][0], d, bp.x); fma2(aU[0][1], d, bp.y);
                fma2(aV[0][0], d, bs.x); fma2(aV[0][1], d, bs.y);
                d = dup2(f1);
                fma2(aU[1][0], d, bp.x); fma2(aU[1][1], d, bp.y);
                fma2(aV[1][0], d, bs.x); fma2(aV[1][1], d, bs.y);
                d = dup2(f2);
                fma2(aU[2][0], d, bp.x); fma2(aU[2][1], d, bp.y);
                fma2(aV[2][0], d, bs.x); fma2(aV[2][1], d, bs.y);
                d = dup2(f3);
                fma2(aU[3][0], d, bp.x); fma2(aU[3][1], d, bp.y);
                fma2(aV[3][0], d, bs.x); fma2(aV[3][1], d, bs.y);
            }
        }
        #pragma unroll
        for (int i = 0; i < 4; i++) {
            float2 u0 = unpk(aU[i][0]), u1 = unpk(aU[i][1]);
            float2 v0 = unpk(aV[i][0]), v1 = unpk(aV[i][1]);
            *(float4*)&U[(r + i) * 64 + cb] = make_float4(u0.x, u0.y, u1.x, u1.y);
            *(float4*)&V[(r + i) * 64 + cb] = make_float4(v0.x, v0.y, v1.x, v1.y);
        }
        __syncthreads();

        unsigned long long aW[4][2] = {};
        #pragma unroll
        for (int k4 = 0; k4 < 16; k4++) {
            float4 a0 = *(const float4*)&U[(r + 0) * 64 + k4 * 4];
            float4 a1 = *(const float4*)&U[(r + 1) * 64 + k4 * 4];
            float4 a2 = *(const float4*)&U[(r + 2) * 64 + k4 * 4];
            float4 a3 = *(const float4*)&U[(r + 3) * 64 + k4 * 4];
            #pragma unroll
            for (int kk = 0; kk < 4; kk++) {
                float f0 = kk == 0 ? a0.x : kk == 1 ? a0.y : kk == 2 ? a0.z : a0.w;
                float f1 = kk == 0 ? a1.x : kk == 1 ? a1.y : kk == 2 ? a1.z : a1.w;
                float f2 = kk == 0 ? a2.x : kk == 1 ? a2.y : kk == 2 ? a2.z : a2.w;
                float f3 = kk == 0 ? a3.x : kk == 1 ? a3.y : kk == 2 ? a3.z : a3.w;
                ulonglong2 bv = *(const ulonglong2*)&V[(k4 * 4 + kk) * 64 + cb];
                unsigned long long d;
                d = dup2(f0); fma2(aW[0][0], d, bv.x); fma2(aW[0][1], d, bv.y);
                d = dup2(f1); fma2(aW[1][0], d, bv.x); fma2(aW[1][1], d, bv.y);
                d = dup2(f2); fma2(aW[2][0], d, bv.x); fma2(aW[2][1], d, bv.y);
                d = dup2(f3); fma2(aW[3][0], d, bv.x); fma2(aW[3][1], d, bv.y);
            }
        }
        #pragma unroll
        for (int i = 0; i < 4; i++) {
            float2 w0 = unpk(aW[i][0]), w1 = unpk(aW[i][1]);
            float* pr = &P[(r + i) * 64 + cb];
            float4 pv = *(float4*)pr;
            *(float4*)pr = make_float4(1.5f * pv.x - 0.5f * w0.x,
                                       1.5f * pv.y - 0.5f * w0.y,
                                       1.5f * pv.z - 0.5f * w1.x,
                                       1.5f * pv.w - 0.5f * w1.y);
        }
        __syncthreads();
    }

    const float sq = sqrtf(rTr);
    for (int e = tid; e < 4096; e += 256) {
        int c = e >> 6, k = e & 63;
        float wv = P[c * 64 + k] * sq;
        __nv_bfloat16 h = __float2bfloat16(wv);
        __nv_bfloat16 l = __float2bfloat16(wv - __bfloat162float(h));
        g_wmDual[c * 256 + k] = h;
        g_wmDual[c * 256 + 64 + k] = l;
        g_wmDual[c * 256 + 128 + k] = l;
        g_wmDual[c * 256 + 192 + k] = h;
    }
    if (tid < 64) {
        float bs = 0.f;
        #pragma unroll 8
        for (int cp = 0; cp < 64; cp++) bs += P[tid * 64 + cp] * g_mean[cp];
        g_bias[tid] = bs * sq;
    }
}

// ================= Kernel 4: apply via mma.sync dual-stack, pipelined ==============
// Same zero-cost double buffering: wait(0) -> convert -> sync -> issue(i+1) -> mma.
// smem: fp32 stage @0 (33792 B); wmDual [64][WROW] @33792 (33792 B); B tile
// [128][ROWB] @67584 (34816 B); bias @102400. Total 102656 -> occ 2.
#define WS_OFF 33792
#define BT_OFF 67584
#define BIAS_OFF 102400
#define SMEM_A2 102656

__global__ __launch_bounds__(256) void apply_kernel(const float* __restrict__ X,
                                                    float* __restrict__ Y) {
    extern __shared__ float sm[];
    const int tid = threadIdx.x;
    const int lane = tid & 31, w = tid >> 5;
    const int bid = blockIdx.x;
    const int ts = (bid * NT_A) / NBLK;
    const int te = ((bid + 1) * NT_A) / NBLK;

    const uint32_t sbase = smem_u32(sm);
    const uint32_t wsm = sbase + WS_OFF;
    const uint32_t bsm = sbase + BT_OFF;
    float* s_b = (float*)((char*)sm + BIAS_OFF);

    // prologue: wmDual -> smem, bias, issue stage for tile ts
    {
        const uint32_t* src = (const uint32_t*)g_wmDual;   // 8192 u32
        #pragma unroll
        for (int it = 0; it < 32; it++) {
            int idx = it * 256 + tid;
            int row = idx >> 7, col2 = idx & 127;
            uint32_t v = src[idx];
            asm volatile("st.shared.b32 [%0], %1;"
                         :: "r"(wsm + (uint32_t)(row * (WROW / 2) + col2) * 4), "r"(v));
        }
        if (tid < 64) s_b[tid] = g_bias[tid];
    }
    {
        int bb = ts >> 6, l0 = (ts & 63) << 7;
        const float* Xb = X + (size_t)bb * (Cc * Lc) + l0;
        #pragma unroll
        for (int it = 0; it < 8; it++) {
            int p = it * 256 + tid, c2 = p >> 5, l4 = p & 31;
            cpasync16(sbase + (uint32_t)(c2 * GPAD + l4 * 4) * 4,
                      Xb + (size_t)c2 * Lc + l4 * 4);
        }
        CP_COMMIT();
    }

    const int cc = tid >> 2;
    const int lseg = (tid & 3) * 32;
    const uint32_t hi_addr = bsm + (uint32_t)(cc * ROWB + lseg) * 2;
    const uint32_t lo_addr = hi_addr + (uint32_t)(64 * ROWB) * 2;

    const int m0 = (w & 3) * 16;
    const int n0 = (w >> 2) * 64;
    const int frow = (lane & 7) + ((lane >> 3) & 1) * 8;
    const int fcol8 = (lane >> 4) * 8;
    const uint32_t a_base = wsm + (uint32_t)((m0 + frow) * WROW + fcol8) * 2;
    const uint32_t b_base = bsm + (uint32_t)(frow * ROWB + n0 + fcol8) * 2;

    #pragma unroll 1
    for (int i = ts; i < te; i++) {
        const int bb = i >> 6, l0 = (i & 63) << 7;
        CP_WAIT(0);
        __syncthreads();             // stage i visible; prior mma done with B

        // ---- convert stage -> stacked bf16 B ----
        {
            const float* srow = sm + cc * GPAD + lseg;
            #pragma unroll
            for (int j = 0; j < 8; j++) {
                float4 v = *(const float4*)&srow[j * 4];
                split_store(hi_addr + j * 8, lo_addr + j * 8, v);
            }
        }
        __syncthreads();             // stage dead, B ready

        // ---- issue stage for tile i+1 (hides under mma) ----
        if (i + 1 < te) {
            int bb2 = (i + 1) >> 6, l2 = ((i + 1) & 63) << 7;
            const float* Xb = X + (size_t)bb2 * (Cc * Lc) + l2;
            #pragma unroll
            for (int it = 0; it < 8; it++) {
                int p = it * 256 + tid, c2 = p >> 5, l4 = p & 31;
                cpasync16(sbase + (uint32_t)(c2 * GPAD + l4 * 4) * 4,
                          Xb + (size_t)c2 * Lc + l4 * 4);
            }
            CP_COMMIT();
        }

        // ---- HMMA: 8 phys k-steps x (4 B-ldsm + 2 A-ldsm + 16 mma) ----
        float acc[8][4];
        #pragma unroll
        for (int t = 0; t < 8; t++) { acc[t][0] = acc[t][1] = acc[t][2] = acc[t][3] = 0.f; }

        #pragma unroll
        for (int kp = 0; kp < 8; kp++) {
            uint32_t bq[8][2];
            #pragma unroll
            for (int nb = 0; nb < 4; nb++) {
                uint32_t b0, b1, b2, b3;
                ldsm_x4t(b_base + (uint32_t)(kp * 16 * ROWB + nb * 16) * 2,
                         b0, b1, b2, b3);
                bq[2 * nb][0] = b0; bq[2 * nb][1] = b1;
                bq[2 * nb + 1][0] = b2; bq[2 * nb + 1][1] = b3;
            }
            uint32_t a0, a1, a2, a3, c0, c1, c2, c3;
            ldsm_x4(a_base + (uint32_t)(kp * 16) * 2, a0, a1, a2, a3);
            ldsm_x4(a_base + (uint32_t)(128 + kp * 16) * 2, c0, c1, c2, c3);
            #pragma unroll
            for (int j = 0; j < 8; j++) {
                mma16816(acc[j], a0, a1, a2, a3, bq[j][0], bq[j][1]);
                mma16816(acc[j], c0, c1, c2, c3, bq[j][0], bq[j][1]);
            }
        }

        // ---- epilogue: Y fragments - bias ----
        {
            const int r0 = m0 + (lane >> 2);
            const float bb0 = s_b[r0], bb1 = s_b[r0 + 8];
            float* Yb = Y + (size_t)bb * (Cc * Lc) + l0 + n0 + 2 * (lane & 3);
            float* y0 = Yb + (size_t)r0 * Lc;
            float* y1 = Yb + (size_t)(r0 + 8) * Lc;
            #pragma unroll
            for (int j = 0; j < 8; j++) {
                *(float2*)&y0[j * 8] = make_float2(acc[j][0] - bb0, acc[j][1] - bb0);
                *(float2*)&y1[j * 8] = make_float2(acc[j][2] - bb1, acc[j][3] - bb1);
            }
        }
        __syncthreads();             // B consumed before next convert
    }
}

// ================= launch =================
extern "C" void kernel_launch(void* const* d_in, const int* in_sizes, int n_in,
                              void* d_out, int out_size) {
    const float* X = (const float*)d_in[0];
    float* Y = (float*)d_out;

    cudaFuncSetAttribute(gram_kernel, cudaFuncAttributeMaxDynamicSharedMemorySize,
                         SMEM_G);
    cudaFuncSetAttribute(apply_kernel, cudaFuncAttributeMaxDynamicSharedMemorySize,
                         SMEM_A2);
    cudaFuncSetAttribute(solver_kernel, cudaFuncAttributeMaxDynamicSharedMemorySize,
                         SOLVER_SMEM);

    gram_kernel<<<NBLK, 256, SMEM_G>>>(X);
    reduce_kernel<<<129, 256>>>();
    solver_kernel<<<1, 256, SOLVER_SMEM>>>();
    apply_kernel<<<NBLK, 256, SMEM_A2>>>(X, Y);
}